// round 6
// baseline (speedup 1.0000x reference)
#include <cuda_runtime.h>
#include <mma.h>
#include <cstdint>

using namespace nvcuda;

#define D      128
#define LDT    132           // padded smem leading dim (floats)
#define NT     512           // threads per block (16 warps)
#define TM     128           // tile rows
#define GRID   148
#define LN_EPS 1e-5f
#define NMAX   100000

// smem: W1 [128][132], W2 [128][132], A [128][132], rsum[512], rsq[512]
#define WTF        (D * LDT)          // 16896 floats
#define OFF_W1     0
#define OFF_W2     (WTF)
#define OFF_A      (2 * WTF)
#define OFF_RS     (3 * WTF)
#define OFF_RQ     (3 * WTF + 512)
#define SMEM_F     (3 * WTF + 1024)
#define SMEM_BYTES (SMEM_F * 4)       // 206,848 B

// ---------------- static device scratch (no allocations allowed) ----------------
__device__ float g_psrc[(size_t)NMAX * D];
__device__ float g_pdst[(size_t)NMAX * D];

__device__ __forceinline__ float tf32r(float x) { return wmma::__float_to_tf32(x); }

typedef wmma::fragment<wmma::accumulator, 16, 16, 8, float> AccFrag;
typedef wmma::fragment<wmma::matrix_a, 16, 16, 8, wmma::precision::tf32,
                       wmma::row_major> AFrag;
typedef wmma::fragment<wmma::matrix_b, 16, 16, 8, wmma::precision::tf32,
                       wmma::col_major> BFrag;

// stage a [N=128,K=128] row-major weight into padded smem, tf32-rounded.
__device__ __forceinline__ void stage_weight(float* Ws, const float* __restrict__ w,
                                             int tid) {
    #pragma unroll
    for (int it = 0; it < (D * 32) / NT; it++) {
        int i = it * NT + tid;
        int r = i >> 5, c4 = i & 31;
        float4 v = ((const float4*)w)[i];
        v.x = tf32r(v.x); v.y = tf32r(v.y); v.z = tf32r(v.z); v.w = tf32r(v.w);
        *(float4*)(Ws + r * LDT + c4 * 4) = v;
    }
}

// stage TM x 128 rows from global into A tile, tf32-rounded, zero-padded
__device__ __forceinline__ void stage_A(float* A, const float* __restrict__ src,
                                        long r0, int rows, int tid) {
    #pragma unroll
    for (int it = 0; it < (TM * 32) / NT; it++) {
        int i = it * NT + tid;
        int r = i >> 5, c4 = i & 31;
        float4 v = make_float4(0.f, 0.f, 0.f, 0.f);
        if (r < rows) v = ((const float4*)src)[(r0 + r) * 32 + c4];
        v.x = tf32r(v.x); v.y = tf32r(v.y); v.z = tf32r(v.z); v.w = tf32r(v.w);
        *(float4*)(A + r * LDT + c4 * 4) = v;
    }
}

// warp computes its 32x32 region of A(128x128) @ W^T
__device__ __forceinline__ void gemm_tile(const float* A, const float* W,
                                          AccFrag (&c)[2][2], int m0, int n0) {
    #pragma unroll
    for (int i = 0; i < 2; i++)
        #pragma unroll
        for (int j = 0; j < 2; j++) wmma::fill_fragment(c[i][j], 0.f);
    #pragma unroll 4
    for (int k0 = 0; k0 < 16; k0++) {
        AFrag a[2];
        BFrag b[2];
        #pragma unroll
        for (int i = 0; i < 2; i++)
            wmma::load_matrix_sync(a[i], A + (m0 + 16 * i) * LDT + k0 * 8, LDT);
        #pragma unroll
        for (int j = 0; j < 2; j++)
            wmma::load_matrix_sync(b[j], W + (n0 + 16 * j) * LDT + k0 * 8, LDT);
        #pragma unroll
        for (int i = 0; i < 2; i++)
            #pragma unroll
            for (int j = 0; j < 2; j++)
                wmma::mma_sync(c[i][j], a[i], b[j], c[i][j]);
    }
}

__device__ __forceinline__ void store_acc(float* A, AccFrag (&c)[2][2],
                                          int m0, int n0) {
    #pragma unroll
    for (int i = 0; i < 2; i++)
        #pragma unroll
        for (int j = 0; j < 2; j++)
            wmma::store_matrix_sync(A + (m0 + 16 * i) * LDT + (n0 + 16 * j),
                                    c[i][j], LDT, wmma::mem_row_major);
}

// ======================= node projection kernel =======================
__global__ __launch_bounds__(NT, 1) void proj_kernel(const float* __restrict__ src_feat,
                                                     const float* __restrict__ dst_feat,
                                                     const float* __restrict__ w_src,
                                                     const float* __restrict__ w_dst,
                                                     const float* __restrict__ b1,
                                                     int N) {
    extern __shared__ float sm[];
    const int tid = threadIdx.x, wid = tid >> 5;
    const int m0 = (wid >> 2) * 32, n0 = (wid & 3) * 32;
    const int er = tid >> 2, ec = (tid & 3) * 32;

    stage_weight(sm + OFF_W1, w_src, tid);
    stage_weight(sm + OFF_W2, w_dst, tid);
    float* A = sm + OFF_A;

    const int nt = (N + TM - 1) / TM;
    for (int j = blockIdx.x; j < 2 * nt; j += GRID) {
        const int sel = (j >= nt);
        const long r0 = (long)(sel ? j - nt : j) * TM;
        const int rows = min(TM, (int)(N - r0));
        float* outp = sel ? g_pdst : g_psrc;

        __syncthreads();
        stage_A(A, sel ? dst_feat : src_feat, r0, rows, tid);
        __syncthreads();

        AccFrag c[2][2];
        gemm_tile(A, sm + (sel ? OFF_W2 : OFF_W1), c, m0, n0);
        __syncthreads();
        store_acc(A, c, m0, n0);
        __syncthreads();

        if (er < rows) {
            #pragma unroll
            for (int g = 0; g < 8; g++) {
                float4 v = *(float4*)(A + er * LDT + ec + g * 4);
                if (sel) {
                    float4 bb = __ldg((const float4*)&b1[ec + g * 4]);
                    v.x += bb.x; v.y += bb.y; v.z += bb.z; v.w += bb.w;
                }
                ((float4*)outp)[(r0 + er) * 32 + (ec >> 2) + g] = v;
            }
        }
    }
}

// ======================= fused edge kernel =======================
__global__ __launch_bounds__(NT, 1) void edge_kernel(const float* __restrict__ efeat,
                                                     const int* __restrict__ src_idx,
                                                     const int* __restrict__ dst_idx,
                                                     const float* __restrict__ w_efeat,
                                                     const float* __restrict__ w2g,
                                                     const float* __restrict__ b2,
                                                     const float* __restrict__ gamma,
                                                     const float* __restrict__ beta,
                                                     float* __restrict__ out, int E) {
    extern __shared__ float sm[];
    const int tid = threadIdx.x, wid = tid >> 5;
    const int m0 = (wid >> 2) * 32, n0 = (wid & 3) * 32;
    const int er = tid >> 2, ec = (tid & 3) * 32;

    stage_weight(sm + OFF_W1, w_efeat, tid);
    stage_weight(sm + OFF_W2, w2g, tid);
    float* A    = sm + OFF_A;
    float* rsum = sm + OFF_RS;
    float* rsq  = sm + OFF_RQ;

    const int ntiles = (E + TM - 1) / TM;
    for (int t = blockIdx.x; t < ntiles; t += GRID) {
        const long e0 = (long)t * TM;
        const int rows = min(TM, (int)(E - e0));

        __syncthreads();               // protect prior tile's reads of A
        stage_A(A, efeat, e0, rows, tid);
        __syncthreads();

        // ---- GEMM1 ----
        AccFrag c[2][2];
        gemm_tile(A, sm + OFF_W1, c, m0, n0);
        __syncthreads();
        store_acc(A, c, m0, n0);
        __syncthreads();

        // ---- epilogue1: gather + SiLU -> tf32, in place ----
        {
            const long e = e0 + er;
            const bool valid = (er < rows);
            const float4* ps = nullptr;
            const float4* pd = nullptr;
            if (valid) {
                int s  = __ldg(&src_idx[e]);
                int dn = __ldg(&dst_idx[e]);
                ps = (const float4*)&g_psrc[(size_t)s * D + ec];
                pd = (const float4*)&g_pdst[(size_t)dn * D + ec];
            }
            #pragma unroll
            for (int g = 0; g < 8; g++) {
                float4 v = *(float4*)(A + er * LDT + ec + g * 4);
                if (valid) {
                    float4 aa = __ldg(ps + g);
                    float4 bb = __ldg(pd + g);
                    v.x += aa.x + bb.x; v.y += aa.y + bb.y;
                    v.z += aa.z + bb.z; v.w += aa.w + bb.w;
                }
                v.x = tf32r(v.x / (1.f + __expf(-v.x)));
                v.y = tf32r(v.y / (1.f + __expf(-v.y)));
                v.z = tf32r(v.z / (1.f + __expf(-v.z)));
                v.w = tf32r(v.w / (1.f + __expf(-v.w)));
                *(float4*)(A + er * LDT + ec + g * 4) = v;
            }
        }
        __syncthreads();

        // ---- GEMM2 ----
        gemm_tile(A, sm + OFF_W2, c, m0, n0);
        __syncthreads();
        store_acc(A, c, m0, n0);
        __syncthreads();

        // ---- LN pass A: +b2 in place, partial moments ----
        {
            float S = 0.f, Q = 0.f;
            #pragma unroll
            for (int g = 0; g < 8; g++) {
                float4 v = *(float4*)(A + er * LDT + ec + g * 4);
                float4 bb = __ldg((const float4*)&b2[ec + g * 4]);
                v.x += bb.x; v.y += bb.y; v.z += bb.z; v.w += bb.w;
                *(float4*)(A + er * LDT + ec + g * 4) = v;
                S += v.x + v.y + v.z + v.w;
                Q += v.x * v.x + v.y * v.y + v.z * v.z + v.w * v.w;
            }
            rsum[er * 4 + (tid & 3)] = S;
            rsq[er * 4 + (tid & 3)]  = Q;
        }
        __syncthreads();

        // ---- LN pass B: normalize + store ----
        if (er < rows) {
            float S = rsum[er * 4] + rsum[er * 4 + 1] + rsum[er * 4 + 2] + rsum[er * 4 + 3];
            float Q = rsq[er * 4] + rsq[er * 4 + 1] + rsq[er * 4 + 2] + rsq[er * 4 + 3];
            float mean = S * (1.f / D);
            float var  = Q * (1.f / D) - mean * mean;
            float rstd = rsqrtf(var + LN_EPS);
            #pragma unroll
            for (int g = 0; g < 8; g++) {
                float4 v = *(float4*)(A + er * LDT + ec + g * 4);
                float4 gm = __ldg((const float4*)&gamma[ec + g * 4]);
                float4 be = __ldg((const float4*)&beta[ec + g * 4]);
                float4 o;
                o.x = (v.x - mean) * rstd * gm.x + be.x;
                o.y = (v.y - mean) * rstd * gm.y + be.y;
                o.z = (v.z - mean) * rstd * gm.z + be.z;
                o.w = (v.w - mean) * rstd * gm.w + be.w;
                ((float4*)out)[(e0 + er) * 32 + (ec >> 2) + g] = o;
            }
        }
    }
}

// ---------------- launch ----------------
extern "C" void kernel_launch(void* const* d_in, const int* in_sizes, int n_in,
                              void* d_out, int out_size) {
    const float* efeat    = (const float*)d_in[0];
    const float* src_feat = (const float*)d_in[1];
    const float* dst_feat = (const float*)d_in[2];
    const int*   src_idx  = (const int*)d_in[3];
    const int*   dst_idx  = (const int*)d_in[4];
    const float* w_efeat  = (const float*)d_in[5];
    const float* w_src    = (const float*)d_in[6];
    const float* w_dst    = (const float*)d_in[7];
    const float* b1       = (const float*)d_in[8];
    const float* w2       = (const float*)d_in[9];
    const float* b2       = (const float*)d_in[10];
    const float* ln_gamma = (const float*)d_in[11];
    const float* ln_beta  = (const float*)d_in[12];

    const int E = in_sizes[0] / D;
    const int N = in_sizes[1] / D;

    cudaFuncSetAttribute(proj_kernel, cudaFuncAttributeMaxDynamicSharedMemorySize, SMEM_BYTES);
    cudaFuncSetAttribute(edge_kernel, cudaFuncAttributeMaxDynamicSharedMemorySize, SMEM_BYTES);

    proj_kernel<<<GRID, NT, SMEM_BYTES>>>(src_feat, dst_feat, w_src, w_dst, b1, N);
    edge_kernel<<<GRID, NT, SMEM_BYTES>>>(efeat, src_idx, dst_idx, w_efeat, w2,
                                          b2, ln_gamma, ln_beta, (float*)d_out, E);
}

// round 7
// speedup vs baseline: 2.9484x; 2.9484x over previous
#include <cuda_runtime.h>
#include <cstdint>

#define D      128
#define LDT    132            // padded strip leading dim (floats)
#define ROWS   16             // rows per warp strip
#define NT     256            // 8 warps per block
#define NWARP  8
#define GRIDB  296            // 2 per SM, persistent
#define LN_EPS 1e-5f
#define NMAX   100000

// ---------------- static device scratch ----------------
__device__ float  g_psrc[(size_t)NMAX * D];
__device__ float  g_pdst[(size_t)NMAX * D];
// frag-packed weights: [sel][k0:16][n0:16][lane:32] float2 ; sel: 0=w_src,1=w_dst,2=w_efeat,3=w2
__device__ float2 g_wpack[4 * 16 * 16 * 32];

#define STRIP_F    (ROWS * LDT)         // 2112 floats
#define SMEM_BYTES (NWARP * STRIP_F * 4)  // 67,584 B

// ---------------- helpers ----------------
__device__ __forceinline__ uint32_t tf32rn_bits(float x) {
    uint32_t u;
    asm("cvt.rna.tf32.f32 %0, %1;" : "=r"(u) : "f"(x));
    return u;
}
__device__ __forceinline__ uint32_t smem_u32(const void* p) {
    uint32_t a;
    asm("{ .reg .u64 t; cvta.to.shared.u64 t, %1; cvt.u32.u64 %0, t; }"
        : "=r"(a) : "l"(p));
    return a;
}
__device__ __forceinline__ void mma_tf32(float (&c)[4], uint32_t a0, uint32_t a1,
                                         uint32_t a2, uint32_t a3,
                                         uint32_t b0, uint32_t b1) {
    asm volatile(
        "mma.sync.aligned.m16n8k8.row.col.f32.tf32.tf32.f32 "
        "{%0,%1,%2,%3}, {%4,%5,%6,%7}, {%8,%9}, {%0,%1,%2,%3};"
        : "+f"(c[0]), "+f"(c[1]), "+f"(c[2]), "+f"(c[3])
        : "r"(a0), "r"(a1), "r"(a2), "r"(a3), "r"(b0), "r"(b1));
}

// ---------------- weight packing ----------------
__global__ void prep_weights(const float* __restrict__ w_src,
                             const float* __restrict__ w_dst,
                             const float* __restrict__ w_efeat,
                             const float* __restrict__ w2) {
    const float* w = blockIdx.x == 0 ? w_src : blockIdx.x == 1 ? w_dst
                   : blockIdx.x == 2 ? w_efeat : w2;
    float2* outp = g_wpack + (size_t)blockIdx.x * 16 * 16 * 32;
    for (int i = threadIdx.x; i < 16 * 16 * 32; i += blockDim.x) {
        int lane = i & 31, n0 = (i >> 5) & 15, k0 = i >> 9;
        int g = lane >> 2, t = lane & 3;
        // B(row.col) frag for mma: b0 = W[n0*8+g][k0*8+t], b1 = same row, k + 4
        float2 v;
        v.x = __uint_as_float(tf32rn_bits(w[(n0 * 8 + g) * D + k0 * 8 + t]));
        v.y = __uint_as_float(tf32rn_bits(w[(n0 * 8 + g) * D + k0 * 8 + t + 4]));
        outp[i] = v;
    }
}

// ---------------- strip staging ----------------
__device__ __forceinline__ void stage_strip(float* strip, uint32_t sdst,
                                            const float* __restrict__ src,
                                            long r0, long Mlim, int lane) {
    if (r0 + ROWS <= Mlim) {
        #pragma unroll
        for (int r = 0; r < ROWS; r++) {
            asm volatile("cp.async.cg.shared.global [%0], [%1], 16;" ::
                "r"(sdst + (uint32_t)(r * LDT * 4 + lane * 16)),
                "l"(src + (r0 + r) * D + lane * 4));
        }
        asm volatile("cp.async.commit_group;");
        asm volatile("cp.async.wait_group 0;" ::: "memory");
    } else {
        #pragma unroll
        for (int r = 0; r < ROWS; r++) {
            float4 v = make_float4(0.f, 0.f, 0.f, 0.f);
            if (r0 + r < Mlim) v = ((const float4*)src)[(r0 + r) * 32 + lane];
            *(float4*)&strip[r * LDT + lane * 4] = v;
        }
    }
    __syncwarp();
}

// ---------------- warp GEMM: strip(16x128) @ W^T -> acc[16][4] ----------------
__device__ __forceinline__ void warp_gemm(const float* strip,
                                          const float2* __restrict__ wp,
                                          float (&acc)[16][4], int lane) {
    const int g = lane >> 2, t = lane & 3;
    const float* r0p = strip + g * LDT + t;
    const float* r1p = strip + (g + 8) * LDT + t;
    #pragma unroll
    for (int n0 = 0; n0 < 16; n0++)
        #pragma unroll
        for (int j = 0; j < 4; j++) acc[n0][j] = 0.f;
    #pragma unroll
    for (int k0 = 0; k0 < 16; k0++) {
        uint32_t a0 = tf32rn_bits(r0p[k0 * 8]);
        uint32_t a1 = tf32rn_bits(r1p[k0 * 8]);
        uint32_t a2 = tf32rn_bits(r0p[k0 * 8 + 4]);
        uint32_t a3 = tf32rn_bits(r1p[k0 * 8 + 4]);
        #pragma unroll
        for (int n0 = 0; n0 < 16; n0++) {
            float2 bw = __ldg(&wp[(k0 * 16 + n0) * 32 + lane]);
            mma_tf32(acc[n0], a0, a1, a2, a3,
                     __float_as_uint(bw.x), __float_as_uint(bw.y));
        }
    }
}

__device__ __forceinline__ void acc_to_strip(float* strip, float (&acc)[16][4],
                                             int lane) {
    const int g = lane >> 2, t = lane & 3;
    #pragma unroll
    for (int n0 = 0; n0 < 16; n0++) {
        *(float2*)&strip[g * LDT + n0 * 8 + 2 * t]       = make_float2(acc[n0][0], acc[n0][1]);
        *(float2*)&strip[(g + 8) * LDT + n0 * 8 + 2 * t] = make_float2(acc[n0][2], acc[n0][3]);
    }
    __syncwarp();
}

// ======================= node projection kernel =======================
__global__ __launch_bounds__(NT, 2) void proj_kernel(const float* __restrict__ src_feat,
                                                     const float* __restrict__ dst_feat,
                                                     const float* __restrict__ b1,
                                                     int N) {
    extern __shared__ float sm[];
    const int tid = threadIdx.x, wid = tid >> 5, lane = tid & 31;
    float* strip = sm + wid * STRIP_F;
    const uint32_t sdst = smem_u32(strip);
    const int row = lane >> 1, c0 = (lane & 1) * 64;

    const int ns = (N + ROWS - 1) / ROWS;
    for (int sIdx = blockIdx.x * NWARP + wid; sIdx < 2 * ns; sIdx += GRIDB * NWARP) {
        const int sel = (sIdx >= ns);
        const long r0 = (long)(sel ? sIdx - ns : sIdx) * ROWS;
        const float* in = sel ? dst_feat : src_feat;
        float* outp = sel ? g_pdst : g_psrc;
        const float2* wp = g_wpack + (size_t)sel * 16 * 16 * 32;

        stage_strip(strip, sdst, in, r0, N, lane);
        float acc[16][4];
        warp_gemm(strip, wp, acc, lane);
        acc_to_strip(strip, acc, lane);

        long m = r0 + row;
        if (m < N) {
            #pragma unroll
            for (int gq = 0; gq < 16; gq++) {
                float4 v = *(float4*)&strip[row * LDT + c0 + gq * 4];
                if (sel) {
                    float4 bb = __ldg((const float4*)&b1[c0 + gq * 4]);
                    v.x += bb.x; v.y += bb.y; v.z += bb.z; v.w += bb.w;
                }
                ((float4*)outp)[m * 32 + (c0 >> 2) + gq] = v;
            }
        }
        __syncwarp();
    }
}

// ======================= fused edge kernel =======================
__global__ __launch_bounds__(NT, 2) void edge_kernel(const float* __restrict__ efeat,
                                                     const int* __restrict__ src_idx,
                                                     const int* __restrict__ dst_idx,
                                                     const float* __restrict__ b2,
                                                     const float* __restrict__ gamma,
                                                     const float* __restrict__ beta,
                                                     float* __restrict__ out, int E) {
    extern __shared__ float sm[];
    const int tid = threadIdx.x, wid = tid >> 5, lane = tid & 31;
    float* strip = sm + wid * STRIP_F;
    const uint32_t sdst = smem_u32(strip);
    const int row = lane >> 1, c0 = (lane & 1) * 64;
    const float2* wp1 = g_wpack + (size_t)2 * 16 * 16 * 32;   // w_efeat
    const float2* wp2 = g_wpack + (size_t)3 * 16 * 16 * 32;   // w2

    const int ns = (E + ROWS - 1) / ROWS;
    for (int sIdx = blockIdx.x * NWARP + wid; sIdx < ns; sIdx += GRIDB * NWARP) {
        const long e0 = (long)sIdx * ROWS;

        stage_strip(strip, sdst, efeat, e0, E, lane);

        // ---- GEMM1 ----
        float acc[16][4];
        warp_gemm(strip, wp1, acc, lane);
        acc_to_strip(strip, acc, lane);

        // ---- epilogue1: gather + SiLU in place ----
        {
            const long e = e0 + row;
            const bool valid = (e < E);
            const float4* ps = nullptr;
            const float4* pd = nullptr;
            if (valid) {
                int s  = __ldg(&src_idx[e]);
                int dn = __ldg(&dst_idx[e]);
                ps = (const float4*)&g_psrc[(size_t)s * D + c0];
                pd = (const float4*)&g_pdst[(size_t)dn * D + c0];
            }
            #pragma unroll
            for (int gq = 0; gq < 16; gq++) {
                float4 v = *(float4*)&strip[row * LDT + c0 + gq * 4];
                if (valid) {
                    float4 aa = __ldg(ps + gq);
                    float4 bb = __ldg(pd + gq);
                    v.x += aa.x + bb.x; v.y += aa.y + bb.y;
                    v.z += aa.z + bb.z; v.w += aa.w + bb.w;
                }
                v.x = v.x / (1.f + __expf(-v.x));
                v.y = v.y / (1.f + __expf(-v.y));
                v.z = v.z / (1.f + __expf(-v.z));
                v.w = v.w / (1.f + __expf(-v.w));
                *(float4*)&strip[row * LDT + c0 + gq * 4] = v;
            }
        }
        __syncwarp();

        // ---- GEMM2 ----
        warp_gemm(strip, wp2, acc, lane);
        acc_to_strip(strip, acc, lane);

        // ---- epilogue2: +b2, LayerNorm, store ----
        {
            float S = 0.f, Q = 0.f;
            #pragma unroll
            for (int gq = 0; gq < 16; gq++) {
                float4 v = *(float4*)&strip[row * LDT + c0 + gq * 4];
                float4 bb = __ldg((const float4*)&b2[c0 + gq * 4]);
                v.x += bb.x; v.y += bb.y; v.z += bb.z; v.w += bb.w;
                S += v.x + v.y + v.z + v.w;
                Q += v.x * v.x + v.y * v.y + v.z * v.z + v.w * v.w;
            }
            S += __shfl_xor_sync(0xffffffffu, S, 1);
            Q += __shfl_xor_sync(0xffffffffu, Q, 1);
            float mean = S * (1.f / D);
            float var  = Q * (1.f / D) - mean * mean;
            float rstd = rsqrtf(var + LN_EPS);

            const long e = e0 + row;
            if (e < E) {
                #pragma unroll
                for (int gq = 0; gq < 16; gq++) {
                    float4 v = *(float4*)&strip[row * LDT + c0 + gq * 4];
                    float4 bb = __ldg((const float4*)&b2[c0 + gq * 4]);
                    float4 gm = __ldg((const float4*)&gamma[c0 + gq * 4]);
                    float4 be = __ldg((const float4*)&beta[c0 + gq * 4]);
                    float4 o;
                    o.x = (v.x + bb.x - mean) * rstd * gm.x + be.x;
                    o.y = (v.y + bb.y - mean) * rstd * gm.y + be.y;
                    o.z = (v.z + bb.z - mean) * rstd * gm.z + be.z;
                    o.w = (v.w + bb.w - mean) * rstd * gm.w + be.w;
                    ((float4*)out)[e * 32 + (c0 >> 2) + gq] = o;
                }
            }
        }
        __syncwarp();   // strip reused next iteration
    }
}

// ---------------- launch ----------------
extern "C" void kernel_launch(void* const* d_in, const int* in_sizes, int n_in,
                              void* d_out, int out_size) {
    const float* efeat    = (const float*)d_in[0];
    const float* src_feat = (const float*)d_in[1];
    const float* dst_feat = (const float*)d_in[2];
    const int*   src_idx  = (const int*)d_in[3];
    const int*   dst_idx  = (const int*)d_in[4];
    const float* w_efeat  = (const float*)d_in[5];
    const float* w_src    = (const float*)d_in[6];
    const float* w_dst    = (const float*)d_in[7];
    const float* b1       = (const float*)d_in[8];
    const float* w2       = (const float*)d_in[9];
    const float* b2       = (const float*)d_in[10];
    const float* ln_gamma = (const float*)d_in[11];
    const float* ln_beta  = (const float*)d_in[12];

    const int E = in_sizes[0] / D;
    const int N = in_sizes[1] / D;

    cudaFuncSetAttribute(proj_kernel, cudaFuncAttributeMaxDynamicSharedMemorySize, SMEM_BYTES);
    cudaFuncSetAttribute(edge_kernel, cudaFuncAttributeMaxDynamicSharedMemorySize, SMEM_BYTES);

    prep_weights<<<4, 256>>>(w_src, w_dst, w_efeat, w2);
    proj_kernel<<<GRIDB, NT, SMEM_BYTES>>>(src_feat, dst_feat, b1, N);
    edge_kernel<<<GRIDB, NT, SMEM_BYTES>>>(efeat, src_idx, dst_idx,
                                           b2, ln_gamma, ln_beta, (float*)d_out, E);
}

// round 9
// speedup vs baseline: 3.0205x; 1.0244x over previous
#include <cuda_runtime.h>
#include <cstdint>

#define D      128
#define LDT    132            // padded strip leading dim (floats)
#define ROWS   16             // rows per warp strip
#define NT     256            // 8 warps per block
#define NWARP  8
#define GRIDB  296            // 2 per SM, persistent
#define LN_EPS 1e-5f
#define NMAX   100000

// ---------------- static device scratch ----------------
__device__ float  g_psrc[(size_t)NMAX * D];
__device__ float  g_pdst[(size_t)NMAX * D];
// frag-packed weights: [sel][k0:16][npair:8][lane:32] float4
// float4 = (b0 of n0=2p, b1 of n0=2p, b0 of n0=2p+1, b1 of n0=2p+1)
// sel: 0=w_src, 1=w_dst, 2=w_efeat, 3=w2
__device__ float4 g_wpack[4 * 16 * 8 * 32];

#define STRIP_F    (ROWS * LDT)           // 2112 floats
#define SMEM_BYTES (NWARP * STRIP_F * 4)  // 67,584 B

// ---------------- helpers ----------------
__device__ __forceinline__ uint32_t tf32rn_bits(float x) {
    uint32_t u;
    asm("cvt.rna.tf32.f32 %0, %1;" : "=r"(u) : "f"(x));
    return u;
}
__device__ __forceinline__ uint32_t smem_u32(const void* p) {
    uint32_t a;
    asm("{ .reg .u64 t; cvta.to.shared.u64 t, %1; cvt.u32.u64 %0, t; }"
        : "=r"(a) : "l"(p));
    return a;
}
__device__ __forceinline__ void mma_tf32(float (&c)[4], uint32_t a0, uint32_t a1,
                                         uint32_t a2, uint32_t a3,
                                         uint32_t b0, uint32_t b1) {
    asm volatile(
        "mma.sync.aligned.m16n8k8.row.col.f32.tf32.tf32.f32 "
        "{%0,%1,%2,%3}, {%4,%5,%6,%7}, {%8,%9}, {%0,%1,%2,%3};"
        : "+f"(c[0]), "+f"(c[1]), "+f"(c[2]), "+f"(c[3])
        : "r"(a0), "r"(a1), "r"(a2), "r"(a3), "r"(b0), "r"(b1));
}

// ---------------- weight packing ----------------
// grid 16: matrix = blockIdx.x >> 2, quarter = blockIdx.x & 3
__global__ void prep_weights(const float* __restrict__ w_src,
                             const float* __restrict__ w_dst,
                             const float* __restrict__ w_efeat,
                             const float* __restrict__ w2) {
    const int mat = blockIdx.x >> 2;
    const float* w = mat == 0 ? w_src : mat == 1 ? w_dst : mat == 2 ? w_efeat : w2;
    float4* outp = g_wpack + (size_t)mat * 16 * 8 * 32;
    #pragma unroll
    for (int j = 0; j < 4; j++) {
        int i = (blockIdx.x & 3) * 1024 + j * 256 + threadIdx.x;  // 0..4095
        int lane = i & 31, p = (i >> 5) & 7, k0 = i >> 8;
        int g = lane >> 2, t = lane & 3;
        float4 v;
        v.x = __uint_as_float(tf32rn_bits(w[((2 * p)     * 8 + g) * D + k0 * 8 + t]));
        v.y = __uint_as_float(tf32rn_bits(w[((2 * p)     * 8 + g) * D + k0 * 8 + t + 4]));
        v.z = __uint_as_float(tf32rn_bits(w[((2 * p + 1) * 8 + g) * D + k0 * 8 + t]));
        v.w = __uint_as_float(tf32rn_bits(w[((2 * p + 1) * 8 + g) * D + k0 * 8 + t + 4]));
        outp[i] = v;
    }
}

// ---------------- strip staging ----------------
__device__ __forceinline__ void stage_strip(float* strip, uint32_t sdst,
                                            const float* __restrict__ src,
                                            long r0, long Mlim, int lane) {
    if (r0 + ROWS <= Mlim) {
        #pragma unroll
        for (int r = 0; r < ROWS; r++) {
            asm volatile("cp.async.cg.shared.global [%0], [%1], 16;" ::
                "r"(sdst + (uint32_t)(r * LDT * 4 + lane * 16)),
                "l"(src + (r0 + r) * D + lane * 4));
        }
        asm volatile("cp.async.commit_group;");
        asm volatile("cp.async.wait_group 0;" ::: "memory");
    } else {
        #pragma unroll
        for (int r = 0; r < ROWS; r++) {
            float4 v = make_float4(0.f, 0.f, 0.f, 0.f);
            if (r0 + r < Mlim) v = ((const float4*)src)[(r0 + r) * 32 + lane];
            *(float4*)&strip[r * LDT + lane * 4] = v;
        }
    }
    __syncwarp();
}

// ---------------- warp GEMM: strip(16x128) @ W^T -> acc[16][4] ----------------
__device__ __forceinline__ void warp_gemm(const float* strip,
                                          const float4* __restrict__ wp,
                                          float (&acc)[16][4], int lane) {
    const int g = lane >> 2, t = lane & 3;
    const float* r0p = strip + g * LDT + t;
    const float* r1p = strip + (g + 8) * LDT + t;
    #pragma unroll
    for (int n0 = 0; n0 < 16; n0++)
        #pragma unroll
        for (int j = 0; j < 4; j++) acc[n0][j] = 0.f;
    #pragma unroll
    for (int k0 = 0; k0 < 16; k0++) {
        uint32_t a0 = tf32rn_bits(r0p[k0 * 8]);
        uint32_t a1 = tf32rn_bits(r1p[k0 * 8]);
        uint32_t a2 = tf32rn_bits(r0p[k0 * 8 + 4]);
        uint32_t a3 = tf32rn_bits(r1p[k0 * 8 + 4]);
        #pragma unroll
        for (int p = 0; p < 8; p++) {
            float4 bw = __ldg(&wp[(k0 * 8 + p) * 32 + lane]);
            mma_tf32(acc[2 * p], a0, a1, a2, a3,
                     __float_as_uint(bw.x), __float_as_uint(bw.y));
            mma_tf32(acc[2 * p + 1], a0, a1, a2, a3,
                     __float_as_uint(bw.z), __float_as_uint(bw.w));
        }
    }
}

__device__ __forceinline__ void acc_to_strip(float* strip, float (&acc)[16][4],
                                             int lane) {
    const int g = lane >> 2, t = lane & 3;
    #pragma unroll
    for (int n0 = 0; n0 < 16; n0++) {
        *(float2*)&strip[g * LDT + n0 * 8 + 2 * t]       = make_float2(acc[n0][0], acc[n0][1]);
        *(float2*)&strip[(g + 8) * LDT + n0 * 8 + 2 * t] = make_float2(acc[n0][2], acc[n0][3]);
    }
    __syncwarp();
}

// ======================= node projection kernel =======================
__global__ __launch_bounds__(NT, 2) void proj_kernel(const float* __restrict__ src_feat,
                                                     const float* __restrict__ dst_feat,
                                                     const float* __restrict__ b1,
                                                     int N) {
    extern __shared__ float sm[];
    const int tid = threadIdx.x, wid = tid >> 5, lane = tid & 31;
    float* strip = sm + wid * STRIP_F;
    const uint32_t sdst = smem_u32(strip);
    const int row = lane >> 1, c0 = (lane & 1) * 64;

    const int ns = (N + ROWS - 1) / ROWS;
    for (int sIdx = blockIdx.x * NWARP + wid; sIdx < 2 * ns; sIdx += GRIDB * NWARP) {
        const int sel = (sIdx >= ns);
        const long r0 = (long)(sel ? sIdx - ns : sIdx) * ROWS;
        const float* in = sel ? dst_feat : src_feat;
        float* outp = sel ? g_pdst : g_psrc;
        const float4* wp = g_wpack + (size_t)sel * 16 * 8 * 32;

        stage_strip(strip, sdst, in, r0, N, lane);
        float acc[16][4];
        warp_gemm(strip, wp, acc, lane);
        acc_to_strip(strip, acc, lane);

        long m = r0 + row;
        if (m < N) {
            #pragma unroll
            for (int gq = 0; gq < 16; gq++) {
                float4 v = *(float4*)&strip[row * LDT + c0 + gq * 4];
                if (sel) {
                    float4 bb = __ldg((const float4*)&b1[c0 + gq * 4]);
                    v.x += bb.x; v.y += bb.y; v.z += bb.z; v.w += bb.w;
                }
                ((float4*)outp)[m * 32 + (c0 >> 2) + gq] = v;
            }
        }
        __syncwarp();
    }
}

// ======================= fused edge kernel =======================
__global__ __launch_bounds__(NT, 2) void edge_kernel(const float* __restrict__ efeat,
                                                     const int* __restrict__ src_idx,
                                                     const int* __restrict__ dst_idx,
                                                     const float* __restrict__ b2,
                                                     const float* __restrict__ gamma,
                                                     const float* __restrict__ beta,
                                                     float* __restrict__ out, int E) {
    extern __shared__ float sm[];
    const int tid = threadIdx.x, wid = tid >> 5, lane = tid & 31;
    float* strip = sm + wid * STRIP_F;
    const uint32_t sdst = smem_u32(strip);
    const int row = lane >> 1, c0 = (lane & 1) * 64;
    const float4* wp1 = g_wpack + (size_t)2 * 16 * 8 * 32;   // w_efeat
    const float4* wp2 = g_wpack + (size_t)3 * 16 * 8 * 32;   // w2

    const int ns = (E + ROWS - 1) / ROWS;
    for (int sIdx = blockIdx.x * NWARP + wid; sIdx < ns; sIdx += GRIDB * NWARP) {
        const long e0 = (long)sIdx * ROWS;

        stage_strip(strip, sdst, efeat, e0, E, lane);

        // ---- GEMM1 ----
        float acc[16][4];
        warp_gemm(strip, wp1, acc, lane);
        acc_to_strip(strip, acc, lane);

        // ---- epilogue1: gather + SiLU in place ----
        {
            const long e = e0 + row;
            const bool valid = (e < E);
            const float4* ps = nullptr;
            const float4* pd = nullptr;
            if (valid) {
                int s  = __ldg(&src_idx[e]);
                int dn = __ldg(&dst_idx[e]);
                ps = (const float4*)&g_psrc[(size_t)s * D + c0];
                pd = (const float4*)&g_pdst[(size_t)dn * D + c0];
            }
            #pragma unroll
            for (int gq = 0; gq < 16; gq++) {
                float4 v = *(float4*)&strip[row * LDT + c0 + gq * 4];
                if (valid) {
                    float4 aa = __ldg(ps + gq);
                    float4 bb = __ldg(pd + gq);
                    v.x += aa.x + bb.x; v.y += aa.y + bb.y;
                    v.z += aa.z + bb.z; v.w += aa.w + bb.w;
                }
                v.x = v.x / (1.f + __expf(-v.x));
                v.y = v.y / (1.f + __expf(-v.y));
                v.z = v.z / (1.f + __expf(-v.z));
                v.w = v.w / (1.f + __expf(-v.w));
                *(float4*)&strip[row * LDT + c0 + gq * 4] = v;
            }
        }
        __syncwarp();

        // ---- GEMM2 ----
        warp_gemm(strip, wp2, acc, lane);
        acc_to_strip(strip, acc, lane);

        // ---- epilogue2: +b2, LayerNorm, store ----
        {
            float S = 0.f, Q = 0.f;
            #pragma unroll
            for (int gq = 0; gq < 16; gq++) {
                float4 v = *(float4*)&strip[row * LDT + c0 + gq * 4];
                float4 bb = __ldg((const float4*)&b2[c0 + gq * 4]);
                v.x += bb.x; v.y += bb.y; v.z += bb.z; v.w += bb.w;
                S += v.x + v.y + v.z + v.w;
                Q += v.x * v.x + v.y * v.y + v.z * v.z + v.w * v.w;
            }
            S += __shfl_xor_sync(0xffffffffu, S, 1);
            Q += __shfl_xor_sync(0xffffffffu, Q, 1);
            float mean = S * (1.f / D);
            float var  = Q * (1.f / D) - mean * mean;
            float rstd = rsqrtf(var + LN_EPS);

            const long e = e0 + row;
            if (e < E) {
                #pragma unroll
                for (int gq = 0; gq < 16; gq++) {
                    float4 v = *(float4*)&strip[row * LDT + c0 + gq * 4];
                    float4 bb = __ldg((const float4*)&b2[c0 + gq * 4]);
                    float4 gm = __ldg((const float4*)&gamma[c0 + gq * 4]);
                    float4 be = __ldg((const float4*)&beta[c0 + gq * 4]);
                    float4 o;
                    o.x = (v.x + bb.x - mean) * rstd * gm.x + be.x;
                    o.y = (v.y + bb.y - mean) * rstd * gm.y + be.y;
                    o.z = (v.z + bb.z - mean) * rstd * gm.z + be.z;
                    o.w = (v.w + bb.w - mean) * rstd * gm.w + be.w;
                    ((float4*)out)[e * 32 + (c0 >> 2) + gq] = o;
                }
            }
        }
        __syncwarp();   // strip reused next iteration
    }
}

// ---------------- launch ----------------
extern "C" void kernel_launch(void* const* d_in, const int* in_sizes, int n_in,
                              void* d_out, int out_size) {
    const float* efeat    = (const float*)d_in[0];
    const float* src_feat = (const float*)d_in[1];
    const float* dst_feat = (const float*)d_in[2];
    const int*   src_idx  = (const int*)d_in[3];
    const int*   dst_idx  = (const int*)d_in[4];
    const float* w_efeat  = (const float*)d_in[5];
    const float* w_src    = (const float*)d_in[6];
    const float* w_dst    = (const float*)d_in[7];
    const float* b1       = (const float*)d_in[8];
    const float* w2       = (const float*)d_in[9];
    const float* b2       = (const float*)d_in[10];
    const float* ln_gamma = (const float*)d_in[11];
    const float* ln_beta  = (const float*)d_in[12];

    const int E = in_sizes[0] / D;
    const int N = in_sizes[1] / D;

    cudaFuncSetAttribute(proj_kernel, cudaFuncAttributeMaxDynamicSharedMemorySize, SMEM_BYTES);
    cudaFuncSetAttribute(edge_kernel, cudaFuncAttributeMaxDynamicSharedMemorySize, SMEM_BYTES);

    prep_weights<<<16, 256>>>(w_src, w_dst, w_efeat, w2);
    proj_kernel<<<GRIDB, NT, SMEM_BYTES>>>(src_feat, dst_feat, b1, N);
    edge_kernel<<<GRIDB, NT, SMEM_BYTES>>>(efeat, src_idx, dst_idx,
                                           b2, ln_gamma, ln_beta, (float*)d_out, E);
}

// round 14
// speedup vs baseline: 5.8300x; 1.9302x over previous
#include <cuda_runtime.h>
#include <cuda_fp16.h>
#include <cstdint>

#define D      128
#define LDH    136            // padded strip leading dim (halfs)
#define ROWS   16             // rows per warp strip
#define NT     256            // 8 warps per block
#define NWARP  8
#define GRIDB  296            // 2 per SM, persistent
#define LN_EPS 1e-5f
#define NMAX   100000

// ---------------- static device scratch ----------------
__device__ float g_psrc[(size_t)NMAX * D];
__device__ float g_pdst[(size_t)NMAX * D];
// fp16 frag-packed weights: [sel][kk:8][p:8][lane:32] uint4
// uint4 = (b0 of ntile 2p, b1 of 2p, b0 of 2p+1, b1 of 2p+1)
// sel: 0=w_src, 1=w_dst, 2=w_efeat, 3=w2
__device__ uint4 g_wpackh[4 * 8 * 8 * 32];

#define STRIP_H    (ROWS * LDH)                 // 2176 halfs
#define SMEM_BYTES (NWARP * STRIP_H * 2)        // 34,816 B

// ---------------- helpers ----------------
__device__ __forceinline__ void mma_f16(float (&c)[4], uint32_t a0, uint32_t a1,
                                        uint32_t a2, uint32_t a3,
                                        uint32_t b0, uint32_t b1) {
    asm volatile(
        "mma.sync.aligned.m16n8k16.row.col.f32.f16.f16.f32 "
        "{%0,%1,%2,%3}, {%4,%5,%6,%7}, {%8,%9}, {%0,%1,%2,%3};"
        : "+f"(c[0]), "+f"(c[1]), "+f"(c[2]), "+f"(c[3])
        : "r"(a0), "r"(a1), "r"(a2), "r"(a3), "r"(b0), "r"(b1));
}
__device__ __forceinline__ uint32_t h2bits(float x, float y) {
    __half2 h = __floats2half2_rn(x, y);
    return *(uint32_t*)&h;
}

// ---------------- weight packing ----------------
// B[k][n] = W[n][k] (col-major view). m16n8k16 B-frag for lane (g=lane>>2, t=lane&3):
//   b0 = {W[ng][kb+2t],   W[ng][kb+2t+1]}
//   b1 = {W[ng][kb+2t+8], W[ng][kb+2t+9]},  ng = ntile*8+g, kb = kk*16
__global__ void prep_weights(const float* __restrict__ w_src,
                             const float* __restrict__ w_dst,
                             const float* __restrict__ w_efeat,
                             const float* __restrict__ w2) {
    const int mat = blockIdx.x;
    const float* w = mat == 0 ? w_src : mat == 1 ? w_dst : mat == 2 ? w_efeat : w2;
    uint4* outp = g_wpackh + (size_t)mat * 8 * 8 * 32;
    for (int i = threadIdx.x; i < 8 * 8 * 32; i += blockDim.x) {
        int lane = i & 31, p = (i >> 5) & 7, kk = i >> 8;
        int g = lane >> 2, t = lane & 3;
        int kb = kk * 16 + 2 * t;
        uint4 v;
        const float* r0 = w + (size_t)((2 * p)     * 8 + g) * D;
        const float* r1 = w + (size_t)((2 * p + 1) * 8 + g) * D;
        v.x = h2bits(r0[kb],     r0[kb + 1]);
        v.y = h2bits(r0[kb + 8], r0[kb + 9]);
        v.z = h2bits(r1[kb],     r1[kb + 1]);
        v.w = h2bits(r1[kb + 8], r1[kb + 9]);
        outp[i] = v;
    }
}

// ---------------- warp GEMM: strip(16x128 fp16) @ W^T -> acc[16][4] f32 ----------------
__device__ __forceinline__ void warp_gemm_h(const __half* strip,
                                            const uint4* __restrict__ wp,
                                            float (&acc)[16][4], int lane) {
    const int g = lane >> 2, t = lane & 3;
    const int base = g * LDH + 2 * t;
    #pragma unroll
    for (int n0 = 0; n0 < 16; n0++)
        #pragma unroll
        for (int j = 0; j < 4; j++) acc[n0][j] = 0.f;
    #pragma unroll
    for (int kk = 0; kk < 8; kk++) {
        uint32_t a0 = *(const uint32_t*)&strip[base + kk * 16];
        uint32_t a1 = *(const uint32_t*)&strip[base + 8 * LDH + kk * 16];
        uint32_t a2 = *(const uint32_t*)&strip[base + kk * 16 + 8];
        uint32_t a3 = *(const uint32_t*)&strip[base + 8 * LDH + kk * 16 + 8];
        #pragma unroll
        for (int p = 0; p < 8; p++) {
            uint4 bw = __ldg(&wp[(kk * 8 + p) * 32 + lane]);
            mma_f16(acc[2 * p],     a0, a1, a2, a3, bw.x, bw.y);
            mma_f16(acc[2 * p + 1], a0, a1, a2, a3, bw.z, bw.w);
        }
    }
}

// stage 16 full rows from global f32 into fp16 strip
__device__ __forceinline__ void stage_strip_h(__half* strip,
                                              const float* __restrict__ src,
                                              long r0, int lane) {
    #pragma unroll
    for (int r = 0; r < ROWS; r++) {
        float4 v = __ldg((const float4*)src + (r0 + r) * 32 + lane);
        uint2 h = make_uint2(h2bits(v.x, v.y), h2bits(v.z, v.w));
        *(uint2*)&strip[r * LDH + lane * 4] = h;
    }
    __syncwarp();
}

// ======================= node projection kernel =======================
// N = 100000, divisible by 16 -> no row guards needed
__global__ __launch_bounds__(NT, 2) void proj_kernel(const float* __restrict__ src_feat,
                                                     const float* __restrict__ dst_feat,
                                                     const float* __restrict__ b1,
                                                     int N) {
    extern __shared__ __half smh[];
    const int tid = threadIdx.x, wid = tid >> 5, lane = tid & 31;
    __half* strip = smh + wid * STRIP_H;
    const int g = lane >> 2, tc = (lane & 3) * 2;

    const int ns = N / ROWS;
    for (int sIdx = blockIdx.x * NWARP + wid; sIdx < 2 * ns; sIdx += GRIDB * NWARP) {
        const int sel = (sIdx >= ns);
        const long r0 = (long)(sel ? sIdx - ns : sIdx) * ROWS;
        const float* in = sel ? dst_feat : src_feat;
        float* outp = sel ? g_pdst : g_psrc;
        const uint4* wp = g_wpackh + (size_t)sel * 8 * 8 * 32;

        stage_strip_h(strip, in, r0, lane);
        float acc[16][4];
        warp_gemm_h(strip, wp, acc, lane);

        const long mA = r0 + g, mB = r0 + g + 8;
        #pragma unroll
        for (int j = 0; j < 16; j++) {
            int col = j * 8 + tc;
            float bx = 0.f, by = 0.f;
            if (sel) {
                float2 bb = __ldg((const float2*)&b1[col]);
                bx = bb.x; by = bb.y;
            }
            *(float2*)&outp[mA * D + col] = make_float2(acc[j][0] + bx, acc[j][1] + by);
            *(float2*)&outp[mB * D + col] = make_float2(acc[j][2] + bx, acc[j][3] + by);
        }
        __syncwarp();
    }
}

// ======================= fused edge kernel =======================
// E = 1,000,000, divisible by 16 -> no row guards needed
__global__ __launch_bounds__(NT, 2) void edge_kernel(const float* __restrict__ efeat,
                                                     const int* __restrict__ src_idx,
                                                     const int* __restrict__ dst_idx,
                                                     const float* __restrict__ b2,
                                                     const float* __restrict__ gamma,
                                                     const float* __restrict__ beta,
                                                     float* __restrict__ out, int E) {
    extern __shared__ __half smh[];
    const int tid = threadIdx.x, wid = tid >> 5, lane = tid & 31;
    __half* strip = smh + wid * STRIP_H;
    const int g = lane >> 2, tc = (lane & 3) * 2;
    const uint4* wp1 = g_wpackh + (size_t)2 * 8 * 8 * 32;   // w_efeat
    const uint4* wp2 = g_wpackh + (size_t)3 * 8 * 8 * 32;   // w2

    const int ns = E / ROWS;
    for (int sIdx = blockIdx.x * NWARP + wid; sIdx < ns; sIdx += GRIDB * NWARP) {
        const long e0 = (long)sIdx * ROWS;

        // ---- stage + GEMM1 ----
        stage_strip_h(strip, efeat, e0, lane);
        float acc[16][4];
        warp_gemm_h(strip, wp1, acc, lane);

        // ---- epilogue1 (registers): gather + SiLU -> fp16 strip (U) ----
        {
            const int sA = __ldg(&src_idx[e0 + g]);
            const int dA = __ldg(&dst_idx[e0 + g]);
            const int sB = __ldg(&src_idx[e0 + g + 8]);
            const int dB = __ldg(&dst_idx[e0 + g + 8]);
            const float* psA = &g_psrc[(size_t)sA * D];
            const float* pdA = &g_pdst[(size_t)dA * D];
            const float* psB = &g_psrc[(size_t)sB * D];
            const float* pdB = &g_pdst[(size_t)dB * D];
            #pragma unroll
            for (int j = 0; j < 16; j++) {
                int col = j * 8 + tc;
                float2 a1 = __ldg((const float2*)&psA[col]);
                float2 a2 = __ldg((const float2*)&pdA[col]);
                float2 b1v = __ldg((const float2*)&psB[col]);
                float2 b2v = __ldg((const float2*)&pdB[col]);
                float x0 = acc[j][0] + a1.x + a2.x;
                float x1 = acc[j][1] + a1.y + a2.y;
                float x2 = acc[j][2] + b1v.x + b2v.x;
                float x3 = acc[j][3] + b1v.y + b2v.y;
                x0 = x0 / (1.f + __expf(-x0));
                x1 = x1 / (1.f + __expf(-x1));
                x2 = x2 / (1.f + __expf(-x2));
                x3 = x3 / (1.f + __expf(-x3));
                *(uint32_t*)&strip[g * LDH + col]       = h2bits(x0, x1);
                *(uint32_t*)&strip[(g + 8) * LDH + col] = h2bits(x2, x3);
            }
        }
        __syncwarp();

        // ---- GEMM2 ----
        warp_gemm_h(strip, wp2, acc, lane);

        // ---- epilogue2 (registers): +b2, LayerNorm, store ----
        {
            float SA = 0.f, QA = 0.f, SB = 0.f, QB = 0.f;
            #pragma unroll
            for (int j = 0; j < 16; j++) {
                int col = j * 8 + tc;
                float2 bb = __ldg((const float2*)&b2[col]);
                acc[j][0] += bb.x; acc[j][1] += bb.y;
                acc[j][2] += bb.x; acc[j][3] += bb.y;
                SA += acc[j][0] + acc[j][1];
                QA += acc[j][0] * acc[j][0] + acc[j][1] * acc[j][1];
                SB += acc[j][2] + acc[j][3];
                QB += acc[j][2] * acc[j][2] + acc[j][3] * acc[j][3];
            }
            SA += __shfl_xor_sync(0xffffffffu, SA, 1);
            SA += __shfl_xor_sync(0xffffffffu, SA, 2);
            QA += __shfl_xor_sync(0xffffffffu, QA, 1);
            QA += __shfl_xor_sync(0xffffffffu, QA, 2);
            SB += __shfl_xor_sync(0xffffffffu, SB, 1);
            SB += __shfl_xor_sync(0xffffffffu, SB, 2);
            QB += __shfl_xor_sync(0xffffffffu, QB, 1);
            QB += __shfl_xor_sync(0xffffffffu, QB, 2);
            float meanA = SA * (1.f / D);
            float rstdA = rsqrtf(QA * (1.f / D) - meanA * meanA + LN_EPS);
            float meanB = SB * (1.f / D);
            float rstdB = rsqrtf(QB * (1.f / D) - meanB * meanB + LN_EPS);

            float* rowA = out + (e0 + g) * D;
            float* rowB = out + (e0 + g + 8) * D;
            #pragma unroll
            for (int j = 0; j < 16; j++) {
                int col = j * 8 + tc;
                float2 gm = __ldg((const float2*)&gamma[col]);
                float2 be = __ldg((const float2*)&beta[col]);
                *(float2*)&rowA[col] = make_float2(
                    (acc[j][0] - meanA) * rstdA * gm.x + be.x,
                    (acc[j][1] - meanA) * rstdA * gm.y + be.y);
                *(float2*)&rowB[col] = make_float2(
                    (acc[j][2] - meanB) * rstdB * gm.x + be.x,
                    (acc[j][3] - meanB) * rstdB * gm.y + be.y);
            }
        }
        __syncwarp();   // strip reused next iteration
    }
}

// ---------------- launch ----------------
extern "C" void kernel_launch(void* const* d_in, const int* in_sizes, int n_in,
                              void* d_out, int out_size) {
    const float* efeat    = (const float*)d_in[0];
    const float* src_feat = (const float*)d_in[1];
    const float* dst_feat = (const float*)d_in[2];
    const int*   src_idx  = (const int*)d_in[3];
    const int*   dst_idx  = (const int*)d_in[4];
    const float* w_efeat  = (const float*)d_in[5];
    const float* w_src    = (const float*)d_in[6];
    const float* w_dst    = (const float*)d_in[7];
    const float* b1       = (const float*)d_in[8];
    const float* w2       = (const float*)d_in[9];
    const float* b2       = (const float*)d_in[10];
    const float* ln_gamma = (const float*)d_in[11];
    const float* ln_beta  = (const float*)d_in[12];

    const int E = in_sizes[0] / D;
    const int N = in_sizes[1] / D;

    cudaFuncSetAttribute(proj_kernel, cudaFuncAttributeMaxDynamicSharedMemorySize, SMEM_BYTES);
    cudaFuncSetAttribute(edge_kernel, cudaFuncAttributeMaxDynamicSharedMemorySize, SMEM_BYTES);

    prep_weights<<<4, 256>>>(w_src, w_dst, w_efeat, w2);
    proj_kernel<<<GRIDB, NT, SMEM_BYTES>>>(src_feat, dst_feat, b1, N);
    edge_kernel<<<GRIDB, NT, SMEM_BYTES>>>(efeat, src_idx, dst_idx,
                                           b2, ln_gamma, ln_beta, (float*)d_out, E);
}